// round 11
// baseline (speedup 1.0000x reference)
#include <cuda_runtime.h>
#include <cstdint>

#define B_ 2
#define D_ 96
#define H_ 96
#define W_ 96
#define L_ (H_*W_)        // 9216
#define K_ 4
#define N_ 16
#define R_ 6
#define CDIM (R_ + 2*N_)  // 38
#define SEG 8
#define SEGL (L_/SEG)     // 1152
#define SEGL2 (SEGL/2)    // 576

// Scratch (allocation-free: __device__ globals)
__device__ float g_dd[B_*K_*(L_/2)*D_*4];  // [bk][l/2][d][4]
__device__ float g_bc[B_*K_*(L_/2)*N_*4];  // [bk][l/2][n][4]
__device__ float g_y [B_*K_*L_*D_];
__device__ float g_xT[B_*D_*L_];
__device__ float g_hend  [B_*K_*SEG*D_*N_];
__device__ float g_hstart[B_*K_*SEG*D_*N_];
__device__ float g_sd    [B_*K_*SEG*D_];

__device__ __forceinline__ float ex2f(float x){
    float y; asm("ex2.approx.ftz.f32 %0, %1;" : "=f"(y) : "f"(x)); return y;
}
__device__ __forceinline__ void cp16(void* dst_smem, const void* src){
    unsigned s = (unsigned)__cvta_generic_to_shared(dst_smem);
    asm volatile("cp.async.ca.shared.global [%0], [%1], 16;\n" :: "r"(s), "l"(src));
}
__device__ __forceinline__ void cp_commit(){ asm volatile("cp.async.commit_group;\n"); }
template<int n> __device__ __forceinline__ void cp_wait(){
    asm volatile("cp.async.wait_group %0;\n" :: "n"(n));
}
__device__ __forceinline__ void ffma2(unsigned long long& d, unsigned long long a,
                                      unsigned long long b, unsigned long long c){
    asm("fma.rn.f32x2 %0, %1, %2, %3;" : "=l"(d) : "l"(a), "l"(b), "l"(c));
}
__device__ __forceinline__ unsigned long long dup2(float w){
    unsigned long long r; asm("mov.b64 %0, {%1, %1};" : "=l"(r) : "f"(w)); return r;
}
__device__ __forceinline__ float2 unp2(unsigned long long v){
    float2 r; asm("mov.b64 {%0, %1}, %2;" : "=f"(r.x), "=f"(r.y) : "l"(v)); return r;
}

// ---------------------------------------------------------------------------
// Kernel 0: transpose x (h,w) per (b,d)
// ---------------------------------------------------------------------------
__global__ __launch_bounds__(256) void transpose_kernel(const float* __restrict__ x)
{
    __shared__ float t[32][33];
    int bd = blockIdx.x;
    int th = blockIdx.y / 3, tw = blockIdx.y % 3;
    int tx = threadIdx.x, ty = threadIdx.y;
    const float* src = x + (size_t)bd*L_;
    float* dst = g_xT + (size_t)bd*L_;
    int h0 = th*32, w0 = tw*32;
    #pragma unroll
    for (int i = 0; i < 4; i++)
        t[ty + i*8][tx] = src[(h0 + ty + i*8)*W_ + w0 + tx];
    __syncthreads();
    #pragma unroll
    for (int i = 0; i < 4; i++)
        dst[(w0 + ty + i*8)*H_ + h0 + tx] = t[tx][ty + i*8];
}

// ---------------------------------------------------------------------------
// Kernel 1: projection (unchanged from R9)
// ---------------------------------------------------------------------------
#define WSQ_F  (CDIM*100)
#define XT_F   (D_*36)
#define CB_F   (CDIM*33)
__global__ __launch_bounds__(256) void proj_kernel(
    const float* __restrict__ x, const float* __restrict__ xpw,
    const float* __restrict__ dtw, const float* __restrict__ dtb)
{
    extern __shared__ float sm[];
    float* wsq  = sm;
    float* wdT  = wsq + WSQ_F;
    float* sbias= wdT + R_*D_;
    float* xt0  = sbias + D_;
    float* cb0  = xt0 + 2*XT_F;

    int bk = blockIdx.x; int b = bk>>2; int k = bk&3;
    int tid = threadIdx.x;
    int half = tid>>7, htid = tid&127;
    float* xt = xt0 + half*XT_F;
    float* cbuf = cb0 + half*CB_F;
    int l0 = blockIdx.y*64 + half*32;

    for (int i = tid; i < CDIM*D_; i += 256){
        int c = i/D_, d = i - c*D_;
        wsq[c*100+d] = xpw[k*CDIM*D_ + i];
    }
    for (int i = tid; i < D_*R_; i += 256){
        int d = i/R_, r = i - d*R_;
        wdT[r*D_+d] = dtw[k*D_*R_ + i];
    }
    if (tid < D_) sbias[tid] = dtb[k*D_+tid];

    const float* xsrc = ((k&1)==0) ? (x + (size_t)b*D_*L_)
                                   : (g_xT + (size_t)b*D_*L_);
    for (int i = htid; i < D_*32; i += 128){
        int d = i>>5, l = i&31;
        int ll = l0 + l;
        int pos = (k<2) ? ll : (L_-1-ll);
        xt[d*36 + l] = xsrc[(size_t)d*L_ + pos];
    }
    __syncthreads();

    int ci = htid & 15, lj = htid >> 4;
    {
        unsigned long long A0[2]={0ull,0ull}, A1[2]={0ull,0ull}, A2[2]={0ull,0ull};
        #pragma unroll 3
        for (int d4 = 0; d4 < D_/4; d4++){
            float4 w0 = *(const float4*)&wsq[ci*100 + d4*4];
            float4 w1 = *(const float4*)&wsq[(ci+16)*100 + d4*4];
            float4 w2 = (ci<6) ? *(const float4*)&wsq[(ci+32)*100 + d4*4]
                               : make_float4(0.f,0.f,0.f,0.f);
            const float* wq0 = &w0.x; const float* wq1 = &w1.x; const float* wq2 = &w2.x;
            #pragma unroll
            for (int j = 0; j < 4; j++){
                ulonglong2 xp = *(const ulonglong2*)&xt[(d4*4+j)*36 + lj*4];
                unsigned long long b0 = dup2(wq0[j]);
                unsigned long long b1 = dup2(wq1[j]);
                unsigned long long b2 = dup2(wq2[j]);
                ffma2(A0[0], b0, xp.x, A0[0]); ffma2(A0[1], b0, xp.y, A0[1]);
                ffma2(A1[0], b1, xp.x, A1[0]); ffma2(A1[1], b1, xp.y, A1[1]);
                ffma2(A2[0], b2, xp.x, A2[0]); ffma2(A2[1], b2, xp.y, A2[1]);
            }
        }
        #pragma unroll
        for (int q=0;q<2;q++){
            float2 v0 = unp2(A0[q]), v1 = unp2(A1[q]), v2 = unp2(A2[q]);
            int l = lj*4 + q*2;
            cbuf[ci*33 + l]        = v0.x;  cbuf[ci*33 + l + 1]        = v0.y;
            cbuf[(ci+16)*33 + l]   = v1.x;  cbuf[(ci+16)*33 + l + 1]   = v1.y;
            if (ci<6){
                cbuf[(ci+32)*33 + l] = v2.x; cbuf[(ci+32)*33 + l + 1] = v2.y;
            }
        }
    }
    __syncthreads();

    #pragma unroll 4
    for (int it = 0; it < 24; it++){
        int i = it*128 + htid;
        int l = i/96, d = i - l*96;
        float s = sbias[d];
        #pragma unroll
        for (int r=0;r<R_;r++) s = fmaf(cbuf[r*33+l], wdT[r*D_+d], s);
        float dlt = (s > 15.f) ? s : __logf(1.f + __expf(s));
        float u = xt[d*36+l];
        int ll = l0 + l;
        float2 v; v.x = dlt; v.y = dlt*u;
        *(float2*)&g_dd[(((size_t)bk*(L_/2) + (ll>>1))*D_ + d)*4 + (ll&1)*2] = v;
    }
    #pragma unroll
    for (int it = 0; it < 4; it++){
        int i = it*128 + htid;
        int l = i>>4, n = i&15;
        float2 v;
        v.x = cbuf[(R_+n)*33 + l];
        v.y = cbuf[(R_+N_+n)*33 + l];
        int ll = l0 + l;
        *(float2*)&g_bc[(((size_t)bk*(L_/2) + (ll>>1))*N_ + n)*4 + (ll&1)*2] = v;
    }
}

// ---------------------------------------------------------------------------
// Kernel 2A: per-segment recurrence with h0=0 -> h_end0, sum(delta).
// 768 blocks (8 segments per chain group) -> real multi-warp occupancy.
// ---------------------------------------------------------------------------
#define ACH2 32                 // packed rows per chunk
#define ANCH (SEGL2/ACH2)       // 18 chunks per segment
__global__ __launch_bounds__(128) void scanA_kernel(const float* __restrict__ A_logs)
{
    __shared__ __align__(16) float sdd[2*ACH2*32];
    __shared__ __align__(16) float sbc[2*ACH2*64];

    int bx = blockIdx.x;
    int seg = bx & 7; int bkd = bx >> 3;
    int bk = bkd / 12, dblk = bkd % 12; int d0 = dblk*8;
    int k = bk & 3;
    int tid = threadIdx.x;
    int wid = tid>>5, lane = tid&31;
    int g = lane>>4, n = lane&15;
    int cidx = wid*2+g;
    int d = d0 + cidx;
    float Ah = -expf(A_logs[(k*D_+d)*N_ + n]) * 1.4426950408889634f;
    float h = 0.f, sd = 0.f;

    const float* gdd = g_dd + ((size_t)bk*(L_/2) + seg*SEGL2)*D_*4;
    const float* gbc = g_bc + ((size_t)bk*(L_/2) + seg*SEGL2)*N_*4;

    {
        for (int i = tid; i < ACH2*8; i += 128){
            int l2 = i>>3, q = i&7;
            cp16(&sdd[l2*32 + q*4], gdd + ((size_t)l2*D_ + d0)*4 + q*4);
        }
        for (int i = tid; i < ACH2*16; i += 128){
            int l2 = i>>4, q = i&15;
            cp16(&sbc[l2*64 + q*4], gbc + (size_t)l2*N_*4 + q*4);
        }
        cp_commit();
    }

    for (int c = 0; c < ANCH; c++){
        int buf = c & 1;
        if (c+1 < ANCH){
            int lb2 = (c+1)*ACH2;
            for (int i = tid; i < ACH2*8; i += 128){
                int l2 = i>>3, q = i&7;
                cp16(&sdd[(buf^1)*ACH2*32 + l2*32 + q*4],
                     gdd + ((size_t)(lb2+l2)*D_ + d0)*4 + q*4);
            }
            for (int i = tid; i < ACH2*16; i += 128){
                int l2 = i>>4, q = i&15;
                cp16(&sbc[(buf^1)*ACH2*64 + l2*64 + q*4],
                     gbc + (size_t)(lb2+l2)*N_*4 + q*4);
            }
            cp_commit();
            cp_wait<1>();
        } else {
            cp_wait<0>();
        }
        __syncthreads();

        const float4* pdd = (const float4*)(sdd + buf*ACH2*32) + cidx;
        const float4* pbc = (const float4*)(sbc + buf*ACH2*64) + n;
        #pragma unroll 8
        for (int t2 = 0; t2 < ACH2; t2++){
            float4 dd = pdd[t2*8];
            float4 bc = pbc[t2*16];
            h = fmaf(ex2f(dd.x*Ah), h, dd.y*bc.x);
            h = fmaf(ex2f(dd.z*Ah), h, dd.w*bc.z);
            sd += dd.x + dd.z;
        }
        __syncthreads();   // protect buffers for next chunk's cp.async
    }

    int idx = ((bk*SEG+seg)*D_ + d)*N_ + n;
    g_hend[idx] = h;
    if (n == 0) g_sd[(bk*SEG+seg)*D_ + d] = sd;
}

// ---------------------------------------------------------------------------
// Kernel 2B: serial segment fixup: h_start[s+1] = ex2(Ah*sd[s])*h_start[s]+hend0[s]
// ---------------------------------------------------------------------------
__global__ __launch_bounds__(256) void scanB_kernel(const float* __restrict__ A_logs)
{
    int i = blockIdx.x*256 + threadIdx.x;
    if (i >= B_*K_*D_*N_) return;
    int n = i & 15; int d = (i>>4) % D_; int bk = i / (D_*N_);
    int k = bk & 3;
    float Ah = -expf(A_logs[(k*D_+d)*N_ + n]) * 1.4426950408889634f;
    float hs = 0.f;
    #pragma unroll
    for (int s = 0; s < SEG; s++){
        int idx = ((bk*SEG+s)*D_ + d)*N_ + n;
        g_hstart[idx] = hs;
        float P = ex2f(Ah * g_sd[(bk*SEG+s)*D_ + d]);
        hs = fmaf(P, hs, g_hend[idx]);
    }
}

// ---------------------------------------------------------------------------
// Kernel 2C: per-segment full scan with known h_start, producing y.
// 768 blocks, CH=48 (46KB smem -> ~4 blocks/SM).
// ---------------------------------------------------------------------------
#define CCH 48
#define CCH2 (CCH/2)            // 24
#define CNCH (SEGL/CCH)         // 24 chunks per segment
#define PROW 36
#define SDD_F (2*CCH2*32)       // 1536
#define SBC_F (2*CCH2*64)       // 3072
#define SP_F  (CCH2*8*PROW)     // 6912
__global__ __launch_bounds__(128) void scanC_kernel(const float* __restrict__ A_logs)
{
    extern __shared__ float smem[];
    float* sdd = smem;
    float* sbc = smem + SDD_F;
    float* sp  = smem + SDD_F + SBC_F;

    int bx = blockIdx.x;
    int seg = bx & 7; int bkd = bx >> 3;
    int bk = bkd / 12, dblk = bkd % 12; int d0 = dblk*8;
    int k = bk & 3;
    int tid = threadIdx.x;
    int wid = tid>>5, lane = tid&31;
    int g = lane>>4, n = lane&15;
    int cidx = wid*2+g;
    int d = d0 + cidx;
    float Ah = -expf(A_logs[(k*D_+d)*N_ + n]) * 1.4426950408889634f;
    float h = g_hstart[((bk*SEG+seg)*D_ + d)*N_ + n];

    const float* gdd = g_dd + ((size_t)bk*(L_/2) + seg*SEGL2)*D_*4;
    const float* gbc = g_bc + ((size_t)bk*(L_/2) + seg*SEGL2)*N_*4;
    float* gy = g_y + (size_t)bk*L_*D_;

    {
        for (int i = tid; i < CCH2*8; i += 128){
            int l2 = i>>3, q = i&7;
            cp16(&sdd[l2*32 + q*4], gdd + ((size_t)l2*D_ + d0)*4 + q*4);
        }
        for (int i = tid; i < CCH2*16; i += 128){
            int l2 = i>>4, q = i&15;
            cp16(&sbc[l2*64 + q*4], gbc + (size_t)l2*N_*4 + q*4);
        }
        cp_commit();
    }

    float* pp = sp + cidx*PROW + n*2;

    for (int c = 0; c < CNCH; c++){
        int buf = c & 1;
        if (c+1 < CNCH){
            int lb2 = (c+1)*CCH2;
            for (int i = tid; i < CCH2*8; i += 128){
                int l2 = i>>3, q = i&7;
                cp16(&sdd[(buf^1)*CCH2*32 + l2*32 + q*4],
                     gdd + ((size_t)(lb2+l2)*D_ + d0)*4 + q*4);
            }
            for (int i = tid; i < CCH2*16; i += 128){
                int l2 = i>>4, q = i&15;
                cp16(&sbc[(buf^1)*CCH2*64 + l2*64 + q*4],
                     gbc + (size_t)(lb2+l2)*N_*4 + q*4);
            }
            cp_commit();
            cp_wait<1>();
        } else {
            cp_wait<0>();
        }
        __syncthreads();   // S1

        const float4* pdd = (const float4*)(sdd + buf*CCH2*32) + cidx;
        const float4* pbc = (const float4*)(sbc + buf*CCH2*64) + n;

        float4 rawd[2], rawb[2];
        float a0c[4], a1c[4], du0c[4], du1c[4], cy0c[4], cy1c[4];
        #pragma unroll
        for (int j = 0; j < 4; j++){
            float4 dd = pdd[j*8];
            float4 bc = pbc[j*16];
            a0c[j]=ex2f(dd.x*Ah); du0c[j]=dd.y*bc.x; cy0c[j]=bc.y;
            a1c[j]=ex2f(dd.z*Ah); du1c[j]=dd.w*bc.z; cy1c[j]=bc.w;
        }
        rawd[0] = pdd[4*8];  rawb[0] = pbc[4*16];
        rawd[1] = pdd[5*8];  rawb[1] = pbc[5*16];

        #pragma unroll
        for (int t2 = 0; t2 < CCH2; t2++){
            int j = t2 & 3, jr = t2 & 1;
            h = fmaf(a0c[j], h, du0c[j]);
            float p0 = h * cy0c[j];
            h = fmaf(a1c[j], h, du1c[j]);
            float p1 = h * cy1c[j];
            float2 st; st.x = p0; st.y = p1;
            *(float2*)&pp[t2*(8*PROW)] = st;
            if (t2 < CCH2-4){
                float4 dd = rawd[jr], bc = rawb[jr];
                a0c[j]=ex2f(dd.x*Ah); du0c[j]=dd.y*bc.x; cy0c[j]=bc.y;
                a1c[j]=ex2f(dd.z*Ah); du1c[j]=dd.w*bc.z; cy1c[j]=bc.w;
            }
            if (t2 < CCH2-6){
                rawd[jr] = pdd[(t2+6)*8];
                rawb[jr] = pbc[(t2+6)*16];
            }
        }
        __syncthreads();   // S2

        int lbase = seg*SEGL + c*CCH;
        for (int T = tid; T < CCH2*8; T += 128){
            int t2 = T>>3, c8 = T&7;
            const float4* q = (const float4*)&sp[(t2*8 + c8)*PROW];
            float e = 0.f, o = 0.f;
            #pragma unroll
            for (int j = 0; j < 8; j++){
                float4 v = q[j];
                e += v.x + v.z; o += v.y + v.w;
            }
            int l = lbase + t2*2;
            gy[(size_t)l*D_ + d0 + c8]     = e;
            gy[(size_t)(l+1)*D_ + d0 + c8] = o;
        }
    }
}

// ---------------------------------------------------------------------------
// Kernel 3: cross-merge + Ds*x + LayerNorm(D). 256 threads (8 warps).
// ---------------------------------------------------------------------------
__global__ __launch_bounds__(256) void merge_kernel(
    const float* __restrict__ x, const float* __restrict__ Ds,
    const float* __restrict__ nw, const float* __restrict__ nb,
    float* __restrict__ out)
{
    __shared__ float xt[D_*33];
    int tid = threadIdx.x;
    int pix0 = blockIdx.x*32;
    int b = pix0 / L_;
    int rem0 = pix0 - b*L_;

    const float* xb = x + (size_t)b*D_*L_;
    for (int i = tid; i < D_*32; i += 256){
        int dd = i>>5, p = i&31;
        xt[dd*33 + p] = xb[(size_t)dd*L_ + rem0 + p];
    }
    __syncthreads();

    int wid = tid>>5, lane = tid&31;
    for (int pp = wid; pp < 32; pp += 8){
        int rem = rem0 + pp;
        int hh = rem / W_;
        int ww = rem - hh*W_;
        int l_wh = ww*H_ + hh;

        const float* y0 = g_y + ((size_t)(b*4+0)*L_ + rem)*D_;
        const float* y1 = g_y + ((size_t)(b*4+1)*L_ + l_wh)*D_;
        const float* y2 = g_y + ((size_t)(b*4+2)*L_ + (L_-1-rem))*D_;
        const float* y3 = g_y + ((size_t)(b*4+3)*L_ + (L_-1-l_wh))*D_;

        float v[3]; float s = 0.f, ss = 0.f;
        #pragma unroll
        for (int j=0;j<3;j++){
            int dd = lane + 32*j;
            float dsum = Ds[dd] + Ds[D_+dd] + Ds[2*D_+dd] + Ds[3*D_+dd];
            float acc = y0[dd] + y1[dd] + y2[dd] + y3[dd] + xt[dd*33+pp] * dsum;
            v[j] = acc; s += acc; ss = fmaf(acc, acc, ss);
        }
        #pragma unroll
        for (int o=16;o>0;o>>=1){
            s  += __shfl_xor_sync(0xffffffffu, s,  o);
            ss += __shfl_xor_sync(0xffffffffu, ss, o);
        }
        float mu  = s * (1.f/D_);
        float var = ss * (1.f/D_) - mu*mu;
        float rstd = rsqrtf(var + 1e-5f);
        float* op = out + ((size_t)b*L_ + rem)*D_;
        #pragma unroll
        for (int j=0;j<3;j++){
            int dd = lane + 32*j;
            op[dd] = (v[j]-mu)*rstd*nw[dd] + nb[dd];
        }
    }
}

// ---------------------------------------------------------------------------
extern "C" void kernel_launch(void* const* d_in, const int* in_sizes, int n_in,
                              void* d_out, int out_size)
{
    const float* x      = (const float*)d_in[0];
    const float* xpw    = (const float*)d_in[1];
    const float* dtw    = (const float*)d_in[2];
    const float* dtb    = (const float*)d_in[3];
    const float* A_logs = (const float*)d_in[4];
    const float* Ds     = (const float*)d_in[5];
    const float* nw     = (const float*)d_in[6];
    const float* nb     = (const float*)d_in[7];
    float* out = (float*)d_out;

    const int proj_smem = (WSQ_F + R_*D_ + D_ + 2*XT_F + 2*CB_F) * sizeof(float);
    cudaFuncSetAttribute(proj_kernel,
                         cudaFuncAttributeMaxDynamicSharedMemorySize, proj_smem);
    const int scanC_smem = (SDD_F + SBC_F + SP_F) * sizeof(float);
    cudaFuncSetAttribute(scanC_kernel,
                         cudaFuncAttributeMaxDynamicSharedMemorySize, scanC_smem);

    transpose_kernel<<<dim3(B_*D_, 9), dim3(32,8)>>>(x);
    proj_kernel<<<dim3(B_*K_, L_/64), 256, proj_smem>>>(x, xpw, dtw, dtb);
    scanA_kernel<<<B_*K_*12*SEG, 128>>>(A_logs);
    scanB_kernel<<<(B_*K_*D_*N_+255)/256, 256>>>(A_logs);
    scanC_kernel<<<B_*K_*12*SEG, 128, scanC_smem>>>(A_logs);
    merge_kernel<<<B_*L_/32, 256>>>(x, Ds, nw, nb, out);
}